// round 14
// baseline (speedup 1.0000x reference)
#include <cuda_runtime.h>
#include <math.h>

#define BN      40000
#define NPG     10000
#define NB      4
#define G       128
#define UNITS   32
#define FDIM    64

// ---------------- device scratch (no allocations allowed) ----------------
// NOTE: zero-init at module load; g_cnt re-zeroed by lstm_k tail, g_stats by scan_k,
// so the "zeroed at entry" invariant holds on every call including graph replays.
__device__ float g_qkv[6u * (size_t)BN * G];     // Q1,K1,V1,Q2,K2,V2 (reused x then h)
__device__ float g_xsum[(size_t)BN * G];
__device__ float g_hsum[(size_t)BN * G];
__device__ int   g_cnt[BN];
__device__ int   g_offs[BN + 1];
__device__ int   g_cur[BN];
__device__ int   g_colx[640000];
__device__ float g_stats[2048];                  // x: sum[0:512) ss[512:1024); h: +1024

// ---------------- helpers ----------------
__device__ __forceinline__ float leaky(float v) { return v >= 0.f ? v : 0.2f * v; }

__device__ __forceinline__ unsigned long long pk(float a, float b) {
    unsigned long long r;
    asm("mov.b64 %0, {%1, %2};" : "=l"(r) : "f"(a), "f"(b));
    return r;
}
__device__ __forceinline__ float2 unpk(unsigned long long v) {
    float2 r;
    asm("mov.b64 {%0, %1}, %2;" : "=f"(r.x), "=f"(r.y) : "l"(v));
    return r;
}
__device__ __forceinline__ void fma2(unsigned long long& d, unsigned long long a, unsigned long long b) {
    asm("fma.rn.f32x2 %0, %1, %2, %0;" : "+l"(d) : "l"(a), "l"(b));
}
__device__ __forceinline__ float dot4(float4 a, float4 b) {
    return fmaf(a.x, b.x, fmaf(a.y, b.y, fmaf(a.z, b.z, a.w * b.w)));
}
__device__ __forceinline__ void online_update(float p, float4 v, float& m, float& s, float4& acc) {
    // warp-uniform branch (p, m identical across lanes)
    if (p <= m) {
        float w = __expf(p - m);
        s += w;
        acc.x = fmaf(w, v.x, acc.x); acc.y = fmaf(w, v.y, acc.y);
        acc.z = fmaf(w, v.z, acc.z); acc.w = fmaf(w, v.w, acc.w);
    } else {
        float sc = __expf(m - p);
        s = fmaf(s, sc, 1.f);
        acc.x = fmaf(acc.x, sc, v.x); acc.y = fmaf(acc.y, sc, v.y);
        acc.z = fmaf(acc.z, sc, v.z); acc.w = fmaf(acc.w, sc, v.w);
        m = p;
    }
}
__device__ __forceinline__ float sigm(float x) { return 1.f / (1.f + __expf(-x)); }

// ---------------- CSR build (4 edges per thread, int4 loads) ----------------
__global__ void hist_k(const int* __restrict__ ei, int E) {
    int t = blockIdx.x * 256 + threadIdx.x;
    if (t * 4 < E) {
        int4 r4 = *(const int4*)(ei + t * 4);
        atomicAdd(&g_cnt[r4.x], 1);
        atomicAdd(&g_cnt[r4.y], 1);
        atomicAdd(&g_cnt[r4.z], 1);
        atomicAdd(&g_cnt[r4.w], 1);
    }
}
__global__ void scan_k(int E) {
    __shared__ int sh[1024];
    int t = threadIdx.x;
    if (t < 512) { g_stats[t * 4] = 0.f; g_stats[t * 4 + 1] = 0.f;
                   g_stats[t * 4 + 2] = 0.f; g_stats[t * 4 + 3] = 0.f; }
    int base = t * 40;
    int n = BN - base; n = n < 0 ? 0 : (n > 40 ? 40 : n);
    int s = 0;
    for (int i = 0; i < n; i++) s += g_cnt[base + i];
    sh[t] = s; __syncthreads();
    for (int off = 1; off < 1024; off <<= 1) {
        int v = (t >= off) ? sh[t - off] : 0;
        __syncthreads();
        sh[t] += v;
        __syncthreads();
    }
    int run = sh[t] - s;  // exclusive prefix
    for (int i = 0; i < n; i++) {
        g_offs[base + i] = run; g_cur[base + i] = run;
        run += g_cnt[base + i];
    }
    if (t == 0) g_offs[BN] = E;
}
__global__ void scat_k(const int* __restrict__ ei, int E) {
    int t = blockIdx.x * 256 + threadIdx.x;
    if (t * 4 < E) {
        int4 r4 = *(const int4*)(ei + t * 4);
        int4 c4 = *(const int4*)(ei + E + t * 4);
        g_colx[atomicAdd(&g_cur[r4.x], 1)] = c4.x;
        g_colx[atomicAdd(&g_cur[r4.y], 1)] = c4.y;
        g_colx[atomicAdd(&g_cur[r4.z], 1)] = c4.z;
        g_colx[atomicAdd(&g_cur[r4.w], 1)] = c4.w;
    }
}

// ---------------- GEMM: out[m] = (leaky)(x @ W + b), 6 matrices, f32x2 pipes --------
// 128 threads (4 warps), 64x128 tile, 16 rows per warp: each 512B/warp weight load is
// reused across 16 rows (was 8), halving smem wavefronts per FMA (L1 was 86% busy).
template <int DIN>
__global__ __launch_bounds__(128, 4) void gemm_qkv(
    const float* __restrict__ x,
    const float* __restrict__ w0, const float* __restrict__ w1, const float* __restrict__ w2,
    const float* __restrict__ w3, const float* __restrict__ w4, const float* __restrict__ w5,
    const float* __restrict__ b0, const float* __restrict__ b1,
    const float* __restrict__ b3, const float* __restrict__ b4)
{
    __shared__ __align__(16) float ws[DIN * 128];
    __shared__ __align__(16) float xsT[DIN * 64];
    int tid = threadIdx.x;
    int m = blockIdx.y;
    const float* w = (m == 0) ? w0 : (m == 1) ? w1 : (m == 2) ? w2 : (m == 3) ? w3 : (m == 4) ? w4 : w5;
    const float* bias = (m == 0) ? b0 : (m == 1) ? b1 : (m == 3) ? b3 : (m == 4) ? b4 : (const float*)0;
    bool act = (m % 3) != 2;
    int row0 = blockIdx.x * 64;

    const float4* w4p = (const float4*)w;
    float4* ws4 = (float4*)ws;
    #pragma unroll
    for (int i = tid; i < DIN * 32; i += 128) ws4[i] = w4p[i];

    for (int i4 = tid; i4 < DIN * 16; i4 += 128) {
        int r = (i4 * 4) / DIN, k0 = (i4 * 4) % DIN;
        float4 v = *(const float4*)(x + (size_t)(row0 + r) * DIN + k0);
        float vv[4] = {v.x, v.y, v.z, v.w};
        #pragma unroll
        for (int j = 0; j < 4; j++) {
            int k = k0 + j;
            xsT[k * 64 + ((((r >> 2) ^ (k & 15)) << 2) | (r & 3))] = vv[j];
        }
    }
    __syncthreads();

    int lane = tid & 31, warp = tid >> 5;
    int g0 = warp * 4;                       // 4 consecutive 4-row groups = 16 rows
    unsigned long long acc[16][2];
    #pragma unroll
    for (int r = 0; r < 16; r++) { acc[r][0] = 0ull; acc[r][1] = 0ull; }

    #pragma unroll 8
    for (int k = 0; k < DIN; k++) {
        float4 wv = *(const float4*)&ws[k * 128 + lane * 4];
        unsigned long long w01 = pk(wv.x, wv.y), w23 = pk(wv.z, wv.w);
        int sw = k & 15;
        float4 a0 = *(const float4*)&xsT[k * 64 + (((g0 + 0) ^ sw) << 2)];
        float4 a1 = *(const float4*)&xsT[k * 64 + (((g0 + 1) ^ sw) << 2)];
        float4 a2 = *(const float4*)&xsT[k * 64 + (((g0 + 2) ^ sw) << 2)];
        float4 a3 = *(const float4*)&xsT[k * 64 + (((g0 + 3) ^ sw) << 2)];
        float ar[16] = {a0.x, a0.y, a0.z, a0.w, a1.x, a1.y, a1.z, a1.w,
                        a2.x, a2.y, a2.z, a2.w, a3.x, a3.y, a3.z, a3.w};
        #pragma unroll
        for (int r = 0; r < 16; r++) {
            unsigned long long aa = pk(ar[r], ar[r]);
            fma2(acc[r][0], aa, w01);
            fma2(acc[r][1], aa, w23);
        }
    }

    float4 bv = make_float4(0.f, 0.f, 0.f, 0.f);
    if (bias) bv = ((const float4*)bias)[lane];
    float* out = g_qkv + (size_t)m * (size_t)BN * G;
    #pragma unroll
    for (int r = 0; r < 16; r++) {
        float2 lo = unpk(acc[r][0]), hi = unpk(acc[r][1]);
        float4 res = make_float4(lo.x + bv.x, lo.y + bv.y, hi.x + bv.z, hi.y + bv.w);
        if (act) { res.x = leaky(res.x); res.y = leaky(res.y); res.z = leaky(res.z); res.w = leaky(res.w); }
        *(float4*)(out + (size_t)(row0 + warp * 16 + r) * 128 + lane * 4) = res;
    }
}

// ---------------- fused dual-GAT aggregation (warp per node, online softmax) ----------------
// + fused graph-norm statistics (8 warps = 8 consecutive nodes, one batch since NPG % 8 == 0)
__global__ __launch_bounds__(256) void gat_agg(
    const float* __restrict__ bv1, const float* __restrict__ bv2, int which)
{
    __shared__ float sh_s[8][128];
    __shared__ float sh_q[8][128];

    int warp = threadIdx.x >> 5;
    int wid = blockIdx.x * 8 + warp;     // grid is exactly BN/8 blocks
    int lane = threadIdx.x & 31;
    const float4* B4 = (const float4*)g_qkv;
    const size_t M4 = (size_t)BN * 32;
    size_t selfi = (size_t)wid * 32 + lane;

    float4 q1 = B4[selfi];
    float4 q2 = B4[M4 * 3 + selfi];

    // self loop
    float4 k1 = B4[M4 + selfi];
    float4 k2 = B4[M4 * 4 + selfi];
    float p1 = dot4(q1, k1), p2 = dot4(q2, k2);
    #pragma unroll
    for (int off = 16; off; off >>= 1) {
        p1 += __shfl_xor_sync(0xffffffffu, p1, off);
        p2 += __shfl_xor_sync(0xffffffffu, p2, off);
    }
    float m1 = p1, s1 = 1.f, m2 = p2, s2 = 1.f;
    float4 acc1 = B4[M4 * 2 + selfi];
    float4 acc2 = B4[M4 * 5 + selfi];

    int start = g_offs[wid], end = g_offs[wid + 1];
    for (int base = start; base < end; base += 32) {
        int e = base + lane;
        int cv = (e < end) ? g_colx[e] : 0;
        int cnt = min(32, end - base);
        for (int j = 0; j < cnt; j++) {
            int src = __shfl_sync(0xffffffffu, cv, j);
            size_t si = (size_t)src * 32 + lane;
            float4 kk1 = B4[M4 + si];
            float4 kk2 = B4[M4 * 4 + si];
            float pa = dot4(q1, kk1), pb = dot4(q2, kk2);
            #pragma unroll
            for (int off = 16; off; off >>= 1) {
                pa += __shfl_xor_sync(0xffffffffu, pa, off);
                pb += __shfl_xor_sync(0xffffffffu, pb, off);
            }
            float4 v1 = B4[M4 * 2 + si];
            float4 v2 = B4[M4 * 5 + si];
            online_update(pa, v1, m1, s1, acc1);
            online_update(pb, v2, m2, s2, acc2);
        }
    }

    float r1 = 1.f / s1, r2 = 1.f / s2;
    float4 bb1 = ((const float4*)bv1)[lane];
    float4 bb2 = ((const float4*)bv2)[lane];
    float4 o;
    o.x = acc1.x * r1 + bb1.x + acc2.x * r2 + bb2.x;
    o.y = acc1.y * r1 + bb1.y + acc2.y * r2 + bb2.y;
    o.z = acc1.z * r1 + bb1.z + acc2.z * r2 + bb2.z;
    o.w = acc1.w * r1 + bb1.w + acc2.w * r2 + bb2.w;
    float* outsum = which ? g_hsum : g_xsum;
    *(float4*)(outsum + selfi * 4) = o;

    // ---- fused stats ----
    int c0 = lane * 4;
    sh_s[warp][c0 + 0] = o.x; sh_s[warp][c0 + 1] = o.y;
    sh_s[warp][c0 + 2] = o.z; sh_s[warp][c0 + 3] = o.w;
    sh_q[warp][c0 + 0] = o.x * o.x; sh_q[warp][c0 + 1] = o.y * o.y;
    sh_q[warp][c0 + 2] = o.z * o.z; sh_q[warp][c0 + 3] = o.w * o.w;
    __syncthreads();

    int t = threadIdx.x;
    int c = t & 127, half = t >> 7;           // 0: sum, 1: sumsq
    int b = (blockIdx.x * 8) / NPG;           // whole block in one batch
    int statbase = (which ? 1024 : 0) + half * 512 + b * 128 + c;
    float acc = 0.f;
    const float (*src)[128] = half ? sh_q : sh_s;
    #pragma unroll
    for (int w = 0; w < 8; w++) acc += src[w][c];
    atomicAdd(&g_stats[statbase], acc);
}

// ---------------- fused norm + leaky + LSTM cell (stats finalized inline) ----------------
// Tail also re-zeroes g_cnt so the next graph replay starts from the invariant state.
__global__ __launch_bounds__(256) void lstm_k(
    const float* __restrict__ cell,
    const float* __restrict__ gx_gamma, const float* __restrict__ gx_beta,
    const float* __restrict__ gh_gamma, const float* __restrict__ gh_beta,
    float* __restrict__ out)
{
    int gid = blockIdx.x * 256 + threadIdx.x;
    if (gid < BN) g_cnt[gid] = 0;   // prepare next replay (g_cnt dead after scan_k)
    if (gid >= BN * 32) return;
    int n = gid >> 5, u = gid & 31;
    int b = n / NPG;

    const float invN = 1.f / NPG;
    float xs[4], hs[4];
    #pragma unroll
    for (int q = 0; q < 4; q++) {
        int c = u + 32 * q;
        size_t ix = (size_t)n * 128 + c;
        {
            float s  = g_stats[b * 128 + c];
            float ss = g_stats[512 + b * 128 + c];
            float mean = s * invN;
            float var  = ss * invN - mean * mean;
            float inv  = 1.f / (sqrtf(fmaxf(var, 0.f)) + 1e-5f);
            float xn = (g_xsum[ix] - mean) * inv;
            xs[q] = leaky(fmaf(gx_gamma[ix], xn, gx_beta[ix]));
        }
        {
            float s  = g_stats[1024 + b * 128 + c];
            float ss = g_stats[1536 + b * 128 + c];
            float mean = s * invN;
            float var  = ss * invN - mean * mean;
            float inv  = 1.f / (sqrtf(fmaxf(var, 0.f)) + 1e-5f);
            float xn = (g_hsum[ix] - mean) * inv;
            hs[q] = leaky(fmaf(gh_gamma[ix], xn, gh_beta[ix]));
        }
    }
    // split order: f, o, i, g
    float fg = sigm(xs[0] + hs[0]);
    float og = sigm(xs[1] + hs[1]);
    float ig = sigm(xs[2] + hs[2]);
    float gg = tanhf(xs[3] + hs[3]);
    float cc = fmaf(fg, cell[gid], ig * gg);
    float nh = og * tanhf(cc);
    out[gid] = cc;
    out[(size_t)BN * 32 + gid] = nh;
}

// ---------------- launcher (strictly serial — proven fastest schedule) ----------------
extern "C" void kernel_launch(void* const* d_in, const int* in_sizes, int n_in,
                              void* d_out, int out_size)
{
    const float* x    = (const float*)d_in[0];
    const float* h    = (const float*)d_in[1];
    const float* cell = (const float*)d_in[2];
    const int*   ei   = (const int*)d_in[3];
    const float* gx1_wq = (const float*)d_in[4];  const float* gx1_bq = (const float*)d_in[5];
    const float* gx1_wk = (const float*)d_in[6];  const float* gx1_bk = (const float*)d_in[7];
    const float* gx1_wv = (const float*)d_in[8];  const float* gx1_bv = (const float*)d_in[9];
    const float* gx2_wq = (const float*)d_in[10]; const float* gx2_bq = (const float*)d_in[11];
    const float* gx2_wk = (const float*)d_in[12]; const float* gx2_bk = (const float*)d_in[13];
    const float* gx2_wv = (const float*)d_in[14]; const float* gx2_bv = (const float*)d_in[15];
    const float* gh1_wq = (const float*)d_in[16]; const float* gh1_bq = (const float*)d_in[17];
    const float* gh1_wk = (const float*)d_in[18]; const float* gh1_bk = (const float*)d_in[19];
    const float* gh1_wv = (const float*)d_in[20]; const float* gh1_bv = (const float*)d_in[21];
    const float* gh2_wq = (const float*)d_in[22]; const float* gh2_bq = (const float*)d_in[23];
    const float* gh2_wk = (const float*)d_in[24]; const float* gh2_bk = (const float*)d_in[25];
    const float* gh2_wv = (const float*)d_in[26]; const float* gh2_bv = (const float*)d_in[27];
    const float* gnx_gamma = (const float*)d_in[28];
    const float* gnx_beta  = (const float*)d_in[29];
    const float* gnh_gamma = (const float*)d_in[30];
    const float* gnh_beta  = (const float*)d_in[31];

    int E = in_sizes[3] / 2;

    // CSR build (target-sorted adjacency); g_cnt pre-zeroed (module init / lstm_k tail)
    hist_k<<<(E / 4 + 255) / 256, 256>>>(ei, E);
    scan_k<<<1, 1024>>>(E);
    scat_k<<<(E / 4 + 255) / 256, 256>>>(ei, E);

    // x branch
    gemm_qkv<FDIM><<<dim3(BN / 64, 6), 128>>>(x,
        gx1_wq, gx1_wk, gx1_wv, gx2_wq, gx2_wk, gx2_wv,
        gx1_bq, gx1_bk, gx2_bq, gx2_bk);
    gat_agg<<<BN / 8, 256>>>(gx1_bv, gx2_bv, 0);

    // h branch (reuses g_qkv)
    gemm_qkv<UNITS><<<dim3(BN / 64, 6), 128>>>(h,
        gh1_wq, gh1_wk, gh1_wv, gh2_wq, gh2_wk, gh2_wv,
        gh1_bq, gh1_bk, gh2_bq, gh2_bk);
    gat_agg<<<BN / 8, 256>>>(gh1_bv, gh2_bv, 1);

    lstm_k<<<(BN * 32 + 255) / 256, 256>>>(cell, gnx_gamma, gnx_beta, gnh_gamma, gnh_beta,
                                           (float*)d_out);
}

// round 15
// speedup vs baseline: 1.0075x; 1.0075x over previous
#include <cuda_runtime.h>
#include <math.h>

#define BN      40000
#define NPG     10000
#define NB      4
#define G       128
#define UNITS   32
#define FDIM    64

// ---------------- device scratch (no allocations allowed) ----------------
// NOTE: zero-init at module load; g_cnt re-zeroed by lstm_k tail, g_stats by scan_k,
// so the "zeroed at entry" invariant holds on every call including graph replays.
__device__ float g_qkv[6u * (size_t)BN * G];     // Q1,K1,V1,Q2,K2,V2 (reused x then h)
__device__ float g_xsum[(size_t)BN * G];
__device__ float g_hsum[(size_t)BN * G];
__device__ int   g_cnt[BN];
__device__ int   g_offs[BN + 1];
__device__ int   g_cur[BN];
__device__ int   g_colx[640000];
__device__ float g_stats[2048];                  // x: sum[0:512) ss[512:1024); h: +1024

// ---------------- helpers ----------------
__device__ __forceinline__ float leaky(float v) { return v >= 0.f ? v : 0.2f * v; }

__device__ __forceinline__ unsigned long long pk(float a, float b) {
    unsigned long long r;
    asm("mov.b64 %0, {%1, %2};" : "=l"(r) : "f"(a), "f"(b));
    return r;
}
__device__ __forceinline__ float2 unpk(unsigned long long v) {
    float2 r;
    asm("mov.b64 {%0, %1}, %2;" : "=f"(r.x), "=f"(r.y) : "l"(v));
    return r;
}
__device__ __forceinline__ void fma2(unsigned long long& d, unsigned long long a, unsigned long long b) {
    asm("fma.rn.f32x2 %0, %1, %2, %0;" : "+l"(d) : "l"(a), "l"(b));
}
__device__ __forceinline__ float dot4(float4 a, float4 b) {
    return fmaf(a.x, b.x, fmaf(a.y, b.y, fmaf(a.z, b.z, a.w * b.w)));
}
__device__ __forceinline__ void online_update(float p, float4 v, float& m, float& s, float4& acc) {
    // warp-uniform branch (p, m identical across lanes)
    if (p <= m) {
        float w = __expf(p - m);
        s += w;
        acc.x = fmaf(w, v.x, acc.x); acc.y = fmaf(w, v.y, acc.y);
        acc.z = fmaf(w, v.z, acc.z); acc.w = fmaf(w, v.w, acc.w);
    } else {
        float sc = __expf(m - p);
        s = fmaf(s, sc, 1.f);
        acc.x = fmaf(acc.x, sc, v.x); acc.y = fmaf(acc.y, sc, v.y);
        acc.z = fmaf(acc.z, sc, v.z); acc.w = fmaf(acc.w, sc, v.w);
        m = p;
    }
}
__device__ __forceinline__ float sigm(float x) { return 1.f / (1.f + __expf(-x)); }

// ---------------- CSR build (4 edges per thread, int4 loads) ----------------
__global__ void hist_k(const int* __restrict__ ei, int E) {
    int t = blockIdx.x * 256 + threadIdx.x;
    if (t * 4 < E) {
        int4 r4 = *(const int4*)(ei + t * 4);
        atomicAdd(&g_cnt[r4.x], 1);
        atomicAdd(&g_cnt[r4.y], 1);
        atomicAdd(&g_cnt[r4.z], 1);
        atomicAdd(&g_cnt[r4.w], 1);
    }
}
__global__ void scan_k(int E) {
    __shared__ int sh[1024];
    int t = threadIdx.x;
    if (t < 512) { g_stats[t * 4] = 0.f; g_stats[t * 4 + 1] = 0.f;
                   g_stats[t * 4 + 2] = 0.f; g_stats[t * 4 + 3] = 0.f; }
    int base = t * 40;
    int n = BN - base; n = n < 0 ? 0 : (n > 40 ? 40 : n);
    int s = 0;
    for (int i = 0; i < n; i++) s += g_cnt[base + i];
    sh[t] = s; __syncthreads();
    for (int off = 1; off < 1024; off <<= 1) {
        int v = (t >= off) ? sh[t - off] : 0;
        __syncthreads();
        sh[t] += v;
        __syncthreads();
    }
    int run = sh[t] - s;  // exclusive prefix
    for (int i = 0; i < n; i++) {
        g_offs[base + i] = run; g_cur[base + i] = run;
        run += g_cnt[base + i];
    }
    if (t == 0) g_offs[BN] = E;
}
__global__ void scat_k(const int* __restrict__ ei, int E) {
    int t = blockIdx.x * 256 + threadIdx.x;
    if (t * 4 < E) {
        int4 r4 = *(const int4*)(ei + t * 4);
        int4 c4 = *(const int4*)(ei + E + t * 4);
        g_colx[atomicAdd(&g_cur[r4.x], 1)] = c4.x;
        g_colx[atomicAdd(&g_cur[r4.y], 1)] = c4.y;
        g_colx[atomicAdd(&g_cur[r4.z], 1)] = c4.z;
        g_colx[atomicAdd(&g_cur[r4.w], 1)] = c4.w;
    }
}

// ---------------- GEMM: out[m] = (leaky)(x @ W + b), 6 matrices, f32x2 pipes --------
// R13 shape (8 rows/warp, 256 thr) + forced 4 blocks/SM: regs were the sole occupancy
// limiter (80 regs -> 3 blocks = 24 warps = 35% occ, matching ncu). Cap at 64 regs.
template <int DIN>
__global__ __launch_bounds__(256, 4) void gemm_qkv(
    const float* __restrict__ x,
    const float* __restrict__ w0, const float* __restrict__ w1, const float* __restrict__ w2,
    const float* __restrict__ w3, const float* __restrict__ w4, const float* __restrict__ w5,
    const float* __restrict__ b0, const float* __restrict__ b1,
    const float* __restrict__ b3, const float* __restrict__ b4)
{
    __shared__ __align__(16) float ws[DIN * 128];
    __shared__ __align__(16) float xsT[DIN * 64];
    int tid = threadIdx.x;
    int m = blockIdx.y;
    const float* w = (m == 0) ? w0 : (m == 1) ? w1 : (m == 2) ? w2 : (m == 3) ? w3 : (m == 4) ? w4 : w5;
    const float* bias = (m == 0) ? b0 : (m == 1) ? b1 : (m == 3) ? b3 : (m == 4) ? b4 : (const float*)0;
    bool act = (m % 3) != 2;
    int row0 = blockIdx.x * 64;

    const float4* w4p = (const float4*)w;
    float4* ws4 = (float4*)ws;
    #pragma unroll
    for (int i = tid; i < DIN * 32; i += 256) ws4[i] = w4p[i];

    for (int i4 = tid; i4 < DIN * 16; i4 += 256) {
        int r = (i4 * 4) / DIN, k0 = (i4 * 4) % DIN;
        float4 v = *(const float4*)(x + (size_t)(row0 + r) * DIN + k0);
        float vv[4] = {v.x, v.y, v.z, v.w};
        #pragma unroll
        for (int j = 0; j < 4; j++) {
            int k = k0 + j;
            xsT[k * 64 + ((((r >> 2) ^ (k & 15)) << 2) | (r & 3))] = vv[j];
        }
    }
    __syncthreads();

    int lane = tid & 31, warp = tid >> 5;
    int r0 = warp * 8;
    unsigned long long acc[8][2];
    #pragma unroll
    for (int r = 0; r < 8; r++) { acc[r][0] = 0ull; acc[r][1] = 0ull; }

    #pragma unroll 8
    for (int k = 0; k < DIN; k++) {
        float4 wv = *(const float4*)&ws[k * 128 + lane * 4];
        unsigned long long w01 = pk(wv.x, wv.y), w23 = pk(wv.z, wv.w);
        int sw = k & 15;
        float4 a0 = *(const float4*)&xsT[k * 64 + (((r0 >> 2) ^ sw) << 2)];
        float4 a1 = *(const float4*)&xsT[k * 64 + ((((r0 >> 2) + 1) ^ sw) << 2)];
        float ar[8] = {a0.x, a0.y, a0.z, a0.w, a1.x, a1.y, a1.z, a1.w};
        #pragma unroll
        for (int r = 0; r < 8; r++) {
            unsigned long long aa = pk(ar[r], ar[r]);
            fma2(acc[r][0], aa, w01);
            fma2(acc[r][1], aa, w23);
        }
    }

    float4 bv = make_float4(0.f, 0.f, 0.f, 0.f);
    if (bias) bv = ((const float4*)bias)[lane];
    float* out = g_qkv + (size_t)m * (size_t)BN * G;
    #pragma unroll
    for (int r = 0; r < 8; r++) {
        float2 lo = unpk(acc[r][0]), hi = unpk(acc[r][1]);
        float4 res = make_float4(lo.x + bv.x, lo.y + bv.y, hi.x + bv.z, hi.y + bv.w);
        if (act) { res.x = leaky(res.x); res.y = leaky(res.y); res.z = leaky(res.z); res.w = leaky(res.w); }
        *(float4*)(out + (size_t)(row0 + r0 + r) * 128 + lane * 4) = res;
    }
}

// ---------------- fused dual-GAT aggregation (warp per node, online softmax) ----------------
// + fused graph-norm statistics (8 warps = 8 consecutive nodes, one batch since NPG % 8 == 0)
__global__ __launch_bounds__(256) void gat_agg(
    const float* __restrict__ bv1, const float* __restrict__ bv2, int which)
{
    __shared__ float sh_s[8][128];
    __shared__ float sh_q[8][128];

    int warp = threadIdx.x >> 5;
    int wid = blockIdx.x * 8 + warp;     // grid is exactly BN/8 blocks
    int lane = threadIdx.x & 31;
    const float4* B4 = (const float4*)g_qkv;
    const size_t M4 = (size_t)BN * 32;
    size_t selfi = (size_t)wid * 32 + lane;

    float4 q1 = B4[selfi];
    float4 q2 = B4[M4 * 3 + selfi];

    // self loop
    float4 k1 = B4[M4 + selfi];
    float4 k2 = B4[M4 * 4 + selfi];
    float p1 = dot4(q1, k1), p2 = dot4(q2, k2);
    #pragma unroll
    for (int off = 16; off; off >>= 1) {
        p1 += __shfl_xor_sync(0xffffffffu, p1, off);
        p2 += __shfl_xor_sync(0xffffffffu, p2, off);
    }
    float m1 = p1, s1 = 1.f, m2 = p2, s2 = 1.f;
    float4 acc1 = B4[M4 * 2 + selfi];
    float4 acc2 = B4[M4 * 5 + selfi];

    int start = g_offs[wid], end = g_offs[wid + 1];
    for (int base = start; base < end; base += 32) {
        int e = base + lane;
        int cv = (e < end) ? g_colx[e] : 0;
        int cnt = min(32, end - base);
        for (int j = 0; j < cnt; j++) {
            int src = __shfl_sync(0xffffffffu, cv, j);
            size_t si = (size_t)src * 32 + lane;
            float4 kk1 = B4[M4 + si];
            float4 kk2 = B4[M4 * 4 + si];
            float pa = dot4(q1, kk1), pb = dot4(q2, kk2);
            #pragma unroll
            for (int off = 16; off; off >>= 1) {
                pa += __shfl_xor_sync(0xffffffffu, pa, off);
                pb += __shfl_xor_sync(0xffffffffu, pb, off);
            }
            float4 v1 = B4[M4 * 2 + si];
            float4 v2 = B4[M4 * 5 + si];
            online_update(pa, v1, m1, s1, acc1);
            online_update(pb, v2, m2, s2, acc2);
        }
    }

    float r1 = 1.f / s1, r2 = 1.f / s2;
    float4 bb1 = ((const float4*)bv1)[lane];
    float4 bb2 = ((const float4*)bv2)[lane];
    float4 o;
    o.x = acc1.x * r1 + bb1.x + acc2.x * r2 + bb2.x;
    o.y = acc1.y * r1 + bb1.y + acc2.y * r2 + bb2.y;
    o.z = acc1.z * r1 + bb1.z + acc2.z * r2 + bb2.z;
    o.w = acc1.w * r1 + bb1.w + acc2.w * r2 + bb2.w;
    float* outsum = which ? g_hsum : g_xsum;
    *(float4*)(outsum + selfi * 4) = o;

    // ---- fused stats ----
    int c0 = lane * 4;
    sh_s[warp][c0 + 0] = o.x; sh_s[warp][c0 + 1] = o.y;
    sh_s[warp][c0 + 2] = o.z; sh_s[warp][c0 + 3] = o.w;
    sh_q[warp][c0 + 0] = o.x * o.x; sh_q[warp][c0 + 1] = o.y * o.y;
    sh_q[warp][c0 + 2] = o.z * o.z; sh_q[warp][c0 + 3] = o.w * o.w;
    __syncthreads();

    int t = threadIdx.x;
    int c = t & 127, half = t >> 7;           // 0: sum, 1: sumsq
    int b = (blockIdx.x * 8) / NPG;           // whole block in one batch
    int statbase = (which ? 1024 : 0) + half * 512 + b * 128 + c;
    float acc = 0.f;
    const float (*src)[128] = half ? sh_q : sh_s;
    #pragma unroll
    for (int w = 0; w < 8; w++) acc += src[w][c];
    atomicAdd(&g_stats[statbase], acc);
}

// ---------------- fused norm + leaky + LSTM cell (stats finalized inline) ----------------
// Tail also re-zeroes g_cnt so the next graph replay starts from the invariant state.
__global__ __launch_bounds__(256) void lstm_k(
    const float* __restrict__ cell,
    const float* __restrict__ gx_gamma, const float* __restrict__ gx_beta,
    const float* __restrict__ gh_gamma, const float* __restrict__ gh_beta,
    float* __restrict__ out)
{
    int gid = blockIdx.x * 256 + threadIdx.x;
    if (gid < BN) g_cnt[gid] = 0;   // prepare next replay (g_cnt dead after scan_k)
    if (gid >= BN * 32) return;
    int n = gid >> 5, u = gid & 31;
    int b = n / NPG;

    const float invN = 1.f / NPG;
    float xs[4], hs[4];
    #pragma unroll
    for (int q = 0; q < 4; q++) {
        int c = u + 32 * q;
        size_t ix = (size_t)n * 128 + c;
        {
            float s  = g_stats[b * 128 + c];
            float ss = g_stats[512 + b * 128 + c];
            float mean = s * invN;
            float var  = ss * invN - mean * mean;
            float inv  = 1.f / (sqrtf(fmaxf(var, 0.f)) + 1e-5f);
            float xn = (g_xsum[ix] - mean) * inv;
            xs[q] = leaky(fmaf(gx_gamma[ix], xn, gx_beta[ix]));
        }
        {
            float s  = g_stats[1024 + b * 128 + c];
            float ss = g_stats[1536 + b * 128 + c];
            float mean = s * invN;
            float var  = ss * invN - mean * mean;
            float inv  = 1.f / (sqrtf(fmaxf(var, 0.f)) + 1e-5f);
            float xn = (g_hsum[ix] - mean) * inv;
            hs[q] = leaky(fmaf(gh_gamma[ix], xn, gh_beta[ix]));
        }
    }
    // split order: f, o, i, g
    float fg = sigm(xs[0] + hs[0]);
    float og = sigm(xs[1] + hs[1]);
    float ig = sigm(xs[2] + hs[2]);
    float gg = tanhf(xs[3] + hs[3]);
    float cc = fmaf(fg, cell[gid], ig * gg);
    float nh = og * tanhf(cc);
    out[gid] = cc;
    out[(size_t)BN * 32 + gid] = nh;
}

// ---------------- launcher (strictly serial — proven fastest schedule) ----------------
extern "C" void kernel_launch(void* const* d_in, const int* in_sizes, int n_in,
                              void* d_out, int out_size)
{
    const float* x    = (const float*)d_in[0];
    const float* h    = (const float*)d_in[1];
    const float* cell = (const float*)d_in[2];
    const int*   ei   = (const int*)d_in[3];
    const float* gx1_wq = (const float*)d_in[4];  const float* gx1_bq = (const float*)d_in[5];
    const float* gx1_wk = (const float*)d_in[6];  const float* gx1_bk = (const float*)d_in[7];
    const float* gx1_wv = (const float*)d_in[8];  const float* gx1_bv = (const float*)d_in[9];
    const float* gx2_wq = (const float*)d_in[10]; const float* gx2_bq = (const float*)d_in[11];
    const float* gx2_wk = (const float*)d_in[12]; const float* gx2_bk = (const float*)d_in[13];
    const float* gx2_wv = (const float*)d_in[14]; const float* gx2_bv = (const float*)d_in[15];
    const float* gh1_wq = (const float*)d_in[16]; const float* gh1_bq = (const float*)d_in[17];
    const float* gh1_wk = (const float*)d_in[18]; const float* gh1_bk = (const float*)d_in[19];
    const float* gh1_wv = (const float*)d_in[20]; const float* gh1_bv = (const float*)d_in[21];
    const float* gh2_wq = (const float*)d_in[22]; const float* gh2_bq = (const float*)d_in[23];
    const float* gh2_wk = (const float*)d_in[24]; const float* gh2_bk = (const float*)d_in[25];
    const float* gh2_wv = (const float*)d_in[26]; const float* gh2_bv = (const float*)d_in[27];
    const float* gnx_gamma = (const float*)d_in[28];
    const float* gnx_beta  = (const float*)d_in[29];
    const float* gnh_gamma = (const float*)d_in[30];
    const float* gnh_beta  = (const float*)d_in[31];

    int E = in_sizes[3] / 2;

    // CSR build (target-sorted adjacency); g_cnt pre-zeroed (module init / lstm_k tail)
    hist_k<<<(E / 4 + 255) / 256, 256>>>(ei, E);
    scan_k<<<1, 1024>>>(E);
    scat_k<<<(E / 4 + 255) / 256, 256>>>(ei, E);

    // x branch
    gemm_qkv<FDIM><<<dim3(BN / 64, 6), 256>>>(x,
        gx1_wq, gx1_wk, gx1_wv, gx2_wq, gx2_wk, gx2_wv,
        gx1_bq, gx1_bk, gx2_bq, gx2_bk);
    gat_agg<<<BN / 8, 256>>>(gx1_bv, gx2_bv, 0);

    // h branch (reuses g_qkv)
    gemm_qkv<UNITS><<<dim3(BN / 64, 6), 256>>>(h,
        gh1_wq, gh1_wk, gh1_wv, gh2_wq, gh2_wk, gh2_wv,
        gh1_bq, gh1_bk, gh2_bq, gh2_bk);
    gat_agg<<<BN / 8, 256>>>(gh1_bv, gh2_bv, 1);

    lstm_k<<<(BN * 32 + 255) / 256, 256>>>(cell, gnx_gamma, gnx_beta, gnh_gamma, gnh_beta,
                                           (float*)d_out);
}

// round 16
// speedup vs baseline: 1.0309x; 1.0233x over previous
#include <cuda_runtime.h>
#include <math.h>

#define BN      40000
#define NPG     10000
#define NB      4
#define G       128
#define UNITS   32
#define FDIM    64

// ---------------- device scratch (no allocations allowed) ----------------
// NOTE: zero-init at module load; g_cnt re-zeroed by lstm_k tail, g_stats by scan_k,
// so the "zeroed at entry" invariant holds on every call including graph replays.
__device__ float g_qkv[6u * (size_t)BN * G];     // Q1,K1,V1,Q2,K2,V2 (reused x then h)
__device__ float g_xsum[(size_t)BN * G];
__device__ float g_hsum[(size_t)BN * G];
__device__ int   g_cnt[BN];
__device__ int   g_offs[BN + 1];
__device__ int   g_cur[BN];
__device__ int   g_colx[640000];
__device__ float g_stats[2048];                  // x: sum[0:512) ss[512:1024); h: +1024

// ---------------- helpers ----------------
__device__ __forceinline__ float leaky(float v) { return v >= 0.f ? v : 0.2f * v; }

__device__ __forceinline__ unsigned long long pk(float a, float b) {
    unsigned long long r;
    asm("mov.b64 %0, {%1, %2};" : "=l"(r) : "f"(a), "f"(b));
    return r;
}
__device__ __forceinline__ float2 unpk(unsigned long long v) {
    float2 r;
    asm("mov.b64 {%0, %1}, %2;" : "=f"(r.x), "=f"(r.y) : "l"(v));
    return r;
}
__device__ __forceinline__ void fma2(unsigned long long& d, unsigned long long a, unsigned long long b) {
    asm("fma.rn.f32x2 %0, %1, %2, %0;" : "+l"(d) : "l"(a), "l"(b));
}
__device__ __forceinline__ float dot4(float4 a, float4 b) {
    return fmaf(a.x, b.x, fmaf(a.y, b.y, fmaf(a.z, b.z, a.w * b.w)));
}
__device__ __forceinline__ void online_update(float p, float4 v, float& m, float& s, float4& acc) {
    // warp-uniform branch (p, m identical across lanes)
    if (p <= m) {
        float w = __expf(p - m);
        s += w;
        acc.x = fmaf(w, v.x, acc.x); acc.y = fmaf(w, v.y, acc.y);
        acc.z = fmaf(w, v.z, acc.z); acc.w = fmaf(w, v.w, acc.w);
    } else {
        float sc = __expf(m - p);
        s = fmaf(s, sc, 1.f);
        acc.x = fmaf(acc.x, sc, v.x); acc.y = fmaf(acc.y, sc, v.y);
        acc.z = fmaf(acc.z, sc, v.z); acc.w = fmaf(acc.w, sc, v.w);
        m = p;
    }
}
__device__ __forceinline__ float sigm(float x) { return 1.f / (1.f + __expf(-x)); }

// ---------------- CSR build (4 edges per thread, int4 loads) ----------------
__global__ void hist_k(const int* __restrict__ ei, int E) {
    int t = blockIdx.x * 256 + threadIdx.x;
    if (t * 4 < E) {
        int4 r4 = *(const int4*)(ei + t * 4);
        atomicAdd(&g_cnt[r4.x], 1);
        atomicAdd(&g_cnt[r4.y], 1);
        atomicAdd(&g_cnt[r4.z], 1);
        atomicAdd(&g_cnt[r4.w], 1);
    }
}
__global__ void scan_k(int E) {
    __shared__ int sh[1024];
    int t = threadIdx.x;
    if (t < 512) { g_stats[t * 4] = 0.f; g_stats[t * 4 + 1] = 0.f;
                   g_stats[t * 4 + 2] = 0.f; g_stats[t * 4 + 3] = 0.f; }
    int base = t * 40;
    int n = BN - base; n = n < 0 ? 0 : (n > 40 ? 40 : n);
    int s = 0;
    for (int i = 0; i < n; i++) s += g_cnt[base + i];
    sh[t] = s; __syncthreads();
    for (int off = 1; off < 1024; off <<= 1) {
        int v = (t >= off) ? sh[t - off] : 0;
        __syncthreads();
        sh[t] += v;
        __syncthreads();
    }
    int run = sh[t] - s;  // exclusive prefix
    for (int i = 0; i < n; i++) {
        g_offs[base + i] = run; g_cur[base + i] = run;
        run += g_cnt[base + i];
    }
    if (t == 0) g_offs[BN] = E;
}
__global__ void scat_k(const int* __restrict__ ei, int E) {
    int t = blockIdx.x * 256 + threadIdx.x;
    if (t * 4 < E) {
        int4 r4 = *(const int4*)(ei + t * 4);
        int4 c4 = *(const int4*)(ei + E + t * 4);
        g_colx[atomicAdd(&g_cur[r4.x], 1)] = c4.x;
        g_colx[atomicAdd(&g_cur[r4.y], 1)] = c4.y;
        g_colx[atomicAdd(&g_cur[r4.z], 1)] = c4.z;
        g_colx[atomicAdd(&g_cur[r4.w], 1)] = c4.w;
    }
}

// ---------------- GEMM: out[m] = (leaky)(x @ W + b), 6 matrices, f32x2 pipes --------
// R13 shape (8 rows/warp, 256 thr). f32x2 pairs are (row r, row r+1) — aliased
// directly from the LDS.128 result registers (zero movs) — with the weight scalar
// duplicated (4 movs/k vs 10). Same LDS traffic, same FMA count, same per-element
// accumulation order (bitwise-identical output); only ALU/issue pressure drops.
template <int DIN>
__global__ __launch_bounds__(256) void gemm_qkv(
    const float* __restrict__ x,
    const float* __restrict__ w0, const float* __restrict__ w1, const float* __restrict__ w2,
    const float* __restrict__ w3, const float* __restrict__ w4, const float* __restrict__ w5,
    const float* __restrict__ b0, const float* __restrict__ b1,
    const float* __restrict__ b3, const float* __restrict__ b4)
{
    __shared__ __align__(16) float ws[DIN * 128];
    __shared__ __align__(16) float xsT[DIN * 64];
    int tid = threadIdx.x;
    int m = blockIdx.y;
    const float* w = (m == 0) ? w0 : (m == 1) ? w1 : (m == 2) ? w2 : (m == 3) ? w3 : (m == 4) ? w4 : w5;
    const float* bias = (m == 0) ? b0 : (m == 1) ? b1 : (m == 3) ? b3 : (m == 4) ? b4 : (const float*)0;
    bool act = (m % 3) != 2;
    int row0 = blockIdx.x * 64;

    const float4* w4p = (const float4*)w;
    float4* ws4 = (float4*)ws;
    #pragma unroll
    for (int i = tid; i < DIN * 32; i += 256) ws4[i] = w4p[i];

    for (int i4 = tid; i4 < DIN * 16; i4 += 256) {
        int r = (i4 * 4) / DIN, k0 = (i4 * 4) % DIN;
        float4 v = *(const float4*)(x + (size_t)(row0 + r) * DIN + k0);
        float vv[4] = {v.x, v.y, v.z, v.w};
        #pragma unroll
        for (int j = 0; j < 4; j++) {
            int k = k0 + j;
            xsT[k * 64 + ((((r >> 2) ^ (k & 15)) << 2) | (r & 3))] = vv[j];
        }
    }
    __syncthreads();

    int lane = tid & 31, warp = tid >> 5;
    int r0 = warp * 8;
    // acc[p][c]: f32x2 holding (row r0+2p, row r0+2p+1) for column lane*4+c
    unsigned long long acc[4][4];
    #pragma unroll
    for (int p = 0; p < 4; p++)
        #pragma unroll
        for (int c = 0; c < 4; c++) acc[p][c] = 0ull;

    #pragma unroll 16
    for (int k = 0; k < DIN; k++) {
        float4 wv = *(const float4*)&ws[k * 128 + lane * 4];
        unsigned long long wd0 = pk(wv.x, wv.x), wd1 = pk(wv.y, wv.y);
        unsigned long long wd2 = pk(wv.z, wv.z), wd3 = pk(wv.w, wv.w);
        int sw = k & 15;
        // LDS.128 as ulonglong2: .x = rows (4g,4g+1), .y = rows (4g+2,4g+3)
        ulonglong2 a0 = *(const ulonglong2*)&xsT[k * 64 + (((r0 >> 2) ^ sw) << 2)];
        ulonglong2 a1 = *(const ulonglong2*)&xsT[k * 64 + ((((r0 >> 2) + 1) ^ sw) << 2)];
        unsigned long long ap[4] = {a0.x, a0.y, a1.x, a1.y};
        #pragma unroll
        for (int p = 0; p < 4; p++) {
            fma2(acc[p][0], ap[p], wd0);
            fma2(acc[p][1], ap[p], wd1);
            fma2(acc[p][2], ap[p], wd2);
            fma2(acc[p][3], ap[p], wd3);
        }
    }

    float4 bv = make_float4(0.f, 0.f, 0.f, 0.f);
    if (bias) bv = ((const float4*)bias)[lane];
    float* out = g_qkv + (size_t)m * (size_t)BN * G;
    #pragma unroll
    for (int p = 0; p < 4; p++) {
        float2 c0 = unpk(acc[p][0]), c1 = unpk(acc[p][1]);
        float2 c2 = unpk(acc[p][2]), c3 = unpk(acc[p][3]);
        float4 ra = make_float4(c0.x + bv.x, c1.x + bv.y, c2.x + bv.z, c3.x + bv.w);
        float4 rb = make_float4(c0.y + bv.x, c1.y + bv.y, c2.y + bv.z, c3.y + bv.w);
        if (act) {
            ra.x = leaky(ra.x); ra.y = leaky(ra.y); ra.z = leaky(ra.z); ra.w = leaky(ra.w);
            rb.x = leaky(rb.x); rb.y = leaky(rb.y); rb.z = leaky(rb.z); rb.w = leaky(rb.w);
        }
        *(float4*)(out + (size_t)(row0 + r0 + 2 * p)     * 128 + lane * 4) = ra;
        *(float4*)(out + (size_t)(row0 + r0 + 2 * p + 1) * 128 + lane * 4) = rb;
    }
}

// ---------------- fused dual-GAT aggregation (warp per node, online softmax) ----------------
// + fused graph-norm statistics (8 warps = 8 consecutive nodes, one batch since NPG % 8 == 0)
__global__ __launch_bounds__(256) void gat_agg(
    const float* __restrict__ bv1, const float* __restrict__ bv2, int which)
{
    __shared__ float sh_s[8][128];
    __shared__ float sh_q[8][128];

    int warp = threadIdx.x >> 5;
    int wid = blockIdx.x * 8 + warp;     // grid is exactly BN/8 blocks
    int lane = threadIdx.x & 31;
    const float4* B4 = (const float4*)g_qkv;
    const size_t M4 = (size_t)BN * 32;
    size_t selfi = (size_t)wid * 32 + lane;

    float4 q1 = B4[selfi];
    float4 q2 = B4[M4 * 3 + selfi];

    // self loop
    float4 k1 = B4[M4 + selfi];
    float4 k2 = B4[M4 * 4 + selfi];
    float p1 = dot4(q1, k1), p2 = dot4(q2, k2);
    #pragma unroll
    for (int off = 16; off; off >>= 1) {
        p1 += __shfl_xor_sync(0xffffffffu, p1, off);
        p2 += __shfl_xor_sync(0xffffffffu, p2, off);
    }
    float m1 = p1, s1 = 1.f, m2 = p2, s2 = 1.f;
    float4 acc1 = B4[M4 * 2 + selfi];
    float4 acc2 = B4[M4 * 5 + selfi];

    int start = g_offs[wid], end = g_offs[wid + 1];
    for (int base = start; base < end; base += 32) {
        int e = base + lane;
        int cv = (e < end) ? g_colx[e] : 0;
        int cnt = min(32, end - base);
        for (int j = 0; j < cnt; j++) {
            int src = __shfl_sync(0xffffffffu, cv, j);
            size_t si = (size_t)src * 32 + lane;
            float4 kk1 = B4[M4 + si];
            float4 kk2 = B4[M4 * 4 + si];
            float pa = dot4(q1, kk1), pb = dot4(q2, kk2);
            #pragma unroll
            for (int off = 16; off; off >>= 1) {
                pa += __shfl_xor_sync(0xffffffffu, pa, off);
                pb += __shfl_xor_sync(0xffffffffu, pb, off);
            }
            float4 v1 = B4[M4 * 2 + si];
            float4 v2 = B4[M4 * 5 + si];
            online_update(pa, v1, m1, s1, acc1);
            online_update(pb, v2, m2, s2, acc2);
        }
    }

    float r1 = 1.f / s1, r2 = 1.f / s2;
    float4 bb1 = ((const float4*)bv1)[lane];
    float4 bb2 = ((const float4*)bv2)[lane];
    float4 o;
    o.x = acc1.x * r1 + bb1.x + acc2.x * r2 + bb2.x;
    o.y = acc1.y * r1 + bb1.y + acc2.y * r2 + bb2.y;
    o.z = acc1.z * r1 + bb1.z + acc2.z * r2 + bb2.z;
    o.w = acc1.w * r1 + bb1.w + acc2.w * r2 + bb2.w;
    float* outsum = which ? g_hsum : g_xsum;
    *(float4*)(outsum + selfi * 4) = o;

    // ---- fused stats ----
    int c0 = lane * 4;
    sh_s[warp][c0 + 0] = o.x; sh_s[warp][c0 + 1] = o.y;
    sh_s[warp][c0 + 2] = o.z; sh_s[warp][c0 + 3] = o.w;
    sh_q[warp][c0 + 0] = o.x * o.x; sh_q[warp][c0 + 1] = o.y * o.y;
    sh_q[warp][c0 + 2] = o.z * o.z; sh_q[warp][c0 + 3] = o.w * o.w;
    __syncthreads();

    int t = threadIdx.x;
    int c = t & 127, half = t >> 7;           // 0: sum, 1: sumsq
    int b = (blockIdx.x * 8) / NPG;           // whole block in one batch
    int statbase = (which ? 1024 : 0) + half * 512 + b * 128 + c;
    float acc = 0.f;
    const float (*src)[128] = half ? sh_q : sh_s;
    #pragma unroll
    for (int w = 0; w < 8; w++) acc += src[w][c];
    atomicAdd(&g_stats[statbase], acc);
}

// ---------------- fused norm + leaky + LSTM cell (stats finalized inline) ----------------
// Tail also re-zeroes g_cnt so the next graph replay starts from the invariant state.
__global__ __launch_bounds__(256) void lstm_k(
    const float* __restrict__ cell,
    const float* __restrict__ gx_gamma, const float* __restrict__ gx_beta,
    const float* __restrict__ gh_gamma, const float* __restrict__ gh_beta,
    float* __restrict__ out)
{
    int gid = blockIdx.x * 256 + threadIdx.x;
    if (gid < BN) g_cnt[gid] = 0;   // prepare next replay (g_cnt dead after scan_k)
    if (gid >= BN * 32) return;
    int n = gid >> 5, u = gid & 31;
    int b = n / NPG;

    const float invN = 1.f / NPG;
    float xs[4], hs[4];
    #pragma unroll
    for (int q = 0; q < 4; q++) {
        int c = u + 32 * q;
        size_t ix = (size_t)n * 128 + c;
        {
            float s  = g_stats[b * 128 + c];
            float ss = g_stats[512 + b * 128 + c];
            float mean = s * invN;
            float var  = ss * invN - mean * mean;
            float inv  = 1.f / (sqrtf(fmaxf(var, 0.f)) + 1e-5f);
            float xn = (g_xsum[ix] - mean) * inv;
            xs[q] = leaky(fmaf(gx_gamma[ix], xn, gx_beta[ix]));
        }
        {
            float s  = g_stats[1024 + b * 128 + c];
            float ss = g_stats[1536 + b * 128 + c];
            float mean = s * invN;
            float var  = ss * invN - mean * mean;
            float inv  = 1.f / (sqrtf(fmaxf(var, 0.f)) + 1e-5f);
            float xn = (g_hsum[ix] - mean) * inv;
            hs[q] = leaky(fmaf(gh_gamma[ix], xn, gh_beta[ix]));
        }
    }
    // split order: f, o, i, g
    float fg = sigm(xs[0] + hs[0]);
    float og = sigm(xs[1] + hs[1]);
    float ig = sigm(xs[2] + hs[2]);
    float gg = tanhf(xs[3] + hs[3]);
    float cc = fmaf(fg, cell[gid], ig * gg);
    float nh = og * tanhf(cc);
    out[gid] = cc;
    out[(size_t)BN * 32 + gid] = nh;
}

// ---------------- launcher (strictly serial — proven fastest schedule) ----------------
extern "C" void kernel_launch(void* const* d_in, const int* in_sizes, int n_in,
                              void* d_out, int out_size)
{
    const float* x    = (const float*)d_in[0];
    const float* h    = (const float*)d_in[1];
    const float* cell = (const float*)d_in[2];
    const int*   ei   = (const int*)d_in[3];
    const float* gx1_wq = (const float*)d_in[4];  const float* gx1_bq = (const float*)d_in[5];
    const float* gx1_wk = (const float*)d_in[6];  const float* gx1_bk = (const float*)d_in[7];
    const float* gx1_wv = (const float*)d_in[8];  const float* gx1_bv = (const float*)d_in[9];
    const float* gx2_wq = (const float*)d_in[10]; const float* gx2_bq = (const float*)d_in[11];
    const float* gx2_wk = (const float*)d_in[12]; const float* gx2_bk = (const float*)d_in[13];
    const float* gx2_wv = (const float*)d_in[14]; const float* gx2_bv = (const float*)d_in[15];
    const float* gh1_wq = (const float*)d_in[16]; const float* gh1_bq = (const float*)d_in[17];
    const float* gh1_wk = (const float*)d_in[18]; const float* gh1_bk = (const float*)d_in[19];
    const float* gh1_wv = (const float*)d_in[20]; const float* gh1_bv = (const float*)d_in[21];
    const float* gh2_wq = (const float*)d_in[22]; const float* gh2_bq = (const float*)d_in[23];
    const float* gh2_wk = (const float*)d_in[24]; const float* gh2_bk = (const float*)d_in[25];
    const float* gh2_wv = (const float*)d_in[26]; const float* gh2_bv = (const float*)d_in[27];
    const float* gnx_gamma = (const float*)d_in[28];
    const float* gnx_beta  = (const float*)d_in[29];
    const float* gnh_gamma = (const float*)d_in[30];
    const float* gnh_beta  = (const float*)d_in[31];

    int E = in_sizes[3] / 2;

    // CSR build (target-sorted adjacency); g_cnt pre-zeroed (module init / lstm_k tail)
    hist_k<<<(E / 4 + 255) / 256, 256>>>(ei, E);
    scan_k<<<1, 1024>>>(E);
    scat_k<<<(E / 4 + 255) / 256, 256>>>(ei, E);

    // x branch
    gemm_qkv<FDIM><<<dim3(BN / 64, 6), 256>>>(x,
        gx1_wq, gx1_wk, gx1_wv, gx2_wq, gx2_wk, gx2_wv,
        gx1_bq, gx1_bk, gx2_bq, gx2_bk);
    gat_agg<<<BN / 8, 256>>>(gx1_bv, gx2_bv, 0);

    // h branch (reuses g_qkv)
    gemm_qkv<UNITS><<<dim3(BN / 64, 6), 256>>>(h,
        gh1_wq, gh1_wk, gh1_wv, gh2_wq, gh2_wk, gh2_wv,
        gh1_bq, gh1_bk, gh2_bq, gh2_bk);
    gat_agg<<<BN / 8, 256>>>(gh1_bv, gh2_bv, 1);

    lstm_k<<<(BN * 32 + 255) / 256, 256>>>(cell, gnx_gamma, gnx_beta, gnh_gamma, gnh_beta,
                                           (float*)d_out);
}